// round 6
// baseline (speedup 1.0000x reference)
#include <cuda_runtime.h>

#define H 512
#define W 512
#define NB 32
#define OUTW 56            // output columns per warp (lanes 0..27 x 2)
#define STRIPS 10          // 10*56 = 560 >= 512
#define YSEGS 16
#define YLEN 32
#define WARPS_TOTAL (STRIPS * NB * YSEGS)   // 5120
#define WPB 2
#define NBLOCKS (WARPS_TOTAL / WPB)         // 2560
#define RP (W / 2)                          // float2 row pitch

__device__ float g_part[NBLOCKS];
__device__ int   g_cnt = 0;

// Pair-channel horizontal 9-window sums. Lane l holds columns 2l (a0), 2l+1 (a1).
#define HSUM9P(a0, a1, hE, hO) do {                          \
    float _p  = (a0) + (a1);                                 \
    float _s  = _p + __shfl_down_sync(0xffffffffu, _p, 1);   \
    float _S4 = _s + __shfl_down_sync(0xffffffffu, _s, 2);   \
    (hE) = _S4  + __shfl_down_sync(0xffffffffu, (a0), 4);    \
    (hO) = (a1) + __shfl_down_sync(0xffffffffu, _S4, 1);     \
} while (0)

__global__ __launch_bounds__(64, 16) void cc_kernel(const float* __restrict__ inp,
                                                    const float* __restrict__ tgt,
                                                    float* __restrict__ out) {
    const int lane = threadIdx.x & 31;
    const int wid  = threadIdx.x >> 5;
    const int w    = blockIdx.x * WPB + wid;

    const int strip = w % STRIPS;
    const int rem   = w / STRIPS;          // 0..511
    const int b     = rem >> 4;            // 0..31
    const int y0    = (rem & 15) << 5;     // 0..480

    const int xs  = strip * OUTW;
    const int gx  = xs - 4 + 2 * lane;
    const bool cok = (unsigned)gx < W;

    const int ocolE = xs + 2 * lane;
    const bool valE = (lane < 28) && (ocolE     < W);
    const bool valO = (lane < 28) && (ocolE + 1 < W);

    const size_t boff = (size_t)b * (H * W) + (cok ? gx : 0);
    const float2* __restrict__ qI = (const float2*)(inp + boff) + (ptrdiff_t)(y0 - 4) * RP;
    const float2* __restrict__ qT = (const float2*)(tgt + boff) + (ptrdiff_t)(y0 - 4) * RP;

    float VA0=0.f, VA1=0.f, VB0=0.f, VB1=0.f, VAA0=0.f, VAA1=0.f,
          VBB0=0.f, VBB1=0.f, VAB0=0.f, VAB1=0.f, acc=0.f;
    const float inv81 = 1.0f / 81.0f;

    // ---- warmup: i = 0..8, add-only; first output at i==8 ----
    #pragma unroll
    for (int i = 0; i < 9; i++) {
        const int gy = y0 - 4 + i;
        float iv0=0.f, iv1=0.f, tv0=0.f, tv1=0.f;
        if (cok && (unsigned)gy < H) {
            const float2 I2 = __ldg(qI);
            const float2 T2 = __ldg(qT);
            iv0 = I2.x; iv1 = I2.y;
            tv0 = fmaf(T2.x, 0.5f, 0.5f);
            tv1 = fmaf(T2.y, 0.5f, 0.5f);
        }
        VA0 += iv0;  VA1 += iv1;  VB0 += tv0;  VB1 += tv1;
        VAA0 = fmaf(iv0, iv0, VAA0);  VAA1 = fmaf(iv1, iv1, VAA1);
        VBB0 = fmaf(tv0, tv0, VBB0);  VBB1 = fmaf(tv1, tv1, VBB1);
        VAB0 = fmaf(iv0, tv0, VAB0);  VAB1 = fmaf(iv1, tv1, VAB1);
        qI += RP; qT += RP;
    }
    // first output row (y0), from warmup sums
    {
        float SAE, SAO, SBE, SBO, SAAE, SAAO, SBBE, SBBO, SABE, SABO;
        HSUM9P(VA0,  VA1,  SAE,  SAO);
        HSUM9P(VB0,  VB1,  SBE,  SBO);
        HSUM9P(VAA0, VAA1, SAAE, SAAO);
        HSUM9P(VBB0, VBB1, SBBE, SBBO);
        HSUM9P(VAB0, VAB1, SABE, SABO);
        {
            const float tA = SAE * inv81, tB = SBE * inv81;
            const float cross = fmaf(-tA, SBE, SABE);
            const float ivar  = fmaf(-tA, SAE, SAAE);
            const float tvar  = fmaf(-tB, SBE, SBBE);
            acc += valE ? __fdividef(cross * cross, fmaf(tvar, ivar, 1e-5f)) : 0.f;
        }
        {
            const float tA = SAO * inv81, tB = SBO * inv81;
            const float cross = fmaf(-tA, SBO, SABO);
            const float ivar  = fmaf(-tA, SAO, SAAO);
            const float tvar  = fmaf(-tB, SBO, SBBO);
            acc += valO ? __fdividef(cross * cross, fmaf(tvar, ivar, 1e-5f)) : 0.f;
        }
    }

    // ---- steady: i = 9..39 (31 iters); enter gy, exit gy-9 (re-load from cache) ----
    #pragma unroll 4
    for (int s = 0; s < 31; s++) {
        const int gy = y0 + 5 + s;
        const bool okn = cok && ((unsigned)gy < H);
        const bool oko = cok && ((unsigned)(gy - 9) < H);

        float iv0=0.f, iv1=0.f, tv0=0.f, tv1=0.f;
        if (okn) {
            const float2 I2 = __ldg(qI);
            const float2 T2 = __ldg(qT);
            iv0 = I2.x; iv1 = I2.y;
            tv0 = fmaf(T2.x, 0.5f, 0.5f);
            tv1 = fmaf(T2.y, 0.5f, 0.5f);
        }
        float oi0=0.f, oi1=0.f, ot0=0.f, ot1=0.f;
        if (oko) {
            const float2 I2 = __ldg(qI - 9 * RP);
            const float2 T2 = __ldg(qT - 9 * RP);
            oi0 = I2.x; oi1 = I2.y;
            ot0 = fmaf(T2.x, 0.5f, 0.5f);
            ot1 = fmaf(T2.y, 0.5f, 0.5f);
        }
        qI += RP; qT += RP;

        VA0 += iv0 - oi0;  VA1 += iv1 - oi1;
        VB0 += tv0 - ot0;  VB1 += tv1 - ot1;
        VAA0 = fmaf(-oi0, oi0, fmaf(iv0, iv0, VAA0));
        VAA1 = fmaf(-oi1, oi1, fmaf(iv1, iv1, VAA1));
        VBB0 = fmaf(-ot0, ot0, fmaf(tv0, tv0, VBB0));
        VBB1 = fmaf(-ot1, ot1, fmaf(tv1, tv1, VBB1));
        VAB0 = fmaf(-oi0, ot0, fmaf(iv0, tv0, VAB0));
        VAB1 = fmaf(-oi1, ot1, fmaf(iv1, tv1, VAB1));

        float SAE, SAO, SBE, SBO, SAAE, SAAO, SBBE, SBBO, SABE, SABO;
        HSUM9P(VA0,  VA1,  SAE,  SAO);
        HSUM9P(VB0,  VB1,  SBE,  SBO);
        HSUM9P(VAA0, VAA1, SAAE, SAAO);
        HSUM9P(VBB0, VBB1, SBBE, SBBO);
        HSUM9P(VAB0, VAB1, SABE, SABO);
        {
            const float tA = SAE * inv81, tB = SBE * inv81;
            const float cross = fmaf(-tA, SBE, SABE);
            const float ivar  = fmaf(-tA, SAE, SAAE);
            const float tvar  = fmaf(-tB, SBE, SBBE);
            acc += valE ? __fdividef(cross * cross, fmaf(tvar, ivar, 1e-5f)) : 0.f;
        }
        {
            const float tA = SAO * inv81, tB = SBO * inv81;
            const float cross = fmaf(-tA, SBO, SABO);
            const float ivar  = fmaf(-tA, SAO, SAAO);
            const float tvar  = fmaf(-tB, SBO, SBBO);
            acc += valO ? __fdividef(cross * cross, fmaf(tvar, ivar, 1e-5f)) : 0.f;
        }
    }

    // ---- reduction: warp -> block -> global partials -> last block finishes ----
    #pragma unroll
    for (int off = 16; off > 0; off >>= 1)
        acc += __shfl_down_sync(0xffffffffu, acc, off);

    __shared__ float sred[WPB];
    __shared__ int   slast;
    if (lane == 0) sred[wid] = acc;
    __syncthreads();
    if (threadIdx.x == 0) {
        g_part[blockIdx.x] = sred[0] + sred[1];
        __threadfence();
        int old = atomicAdd(&g_cnt, 1);
        slast = (old == NBLOCKS - 1) ? 1 : 0;
    }
    __syncthreads();

    if (slast) {
        // 2560 partials = 640 float4; 64 threads -> 10 float4 each
        double d = 0.0;
        const float4* p4 = (const float4*)g_part;
        #pragma unroll
        for (int r = 0; r < 10; r++) {
            const float4 v = p4[threadIdx.x + r * 64];
            d += (double)v.x + (double)v.y + (double)v.z + (double)v.w;
        }
        #pragma unroll
        for (int off = 16; off > 0; off >>= 1)
            d += __shfl_down_sync(0xffffffffu, d, off);
        __shared__ double dred[WPB];
        if (lane == 0) dred[wid] = d;
        __syncthreads();
        if (threadIdx.x == 0) {
            out[0] = (float)(-(dred[0] + dred[1]) / 8388608.0);   // 32*512*512
            g_cnt = 0;                            // reset for next graph replay
        }
    }
}

extern "C" void kernel_launch(void* const* d_in, const int* in_sizes, int n_in,
                              void* d_out, int out_size) {
    const float* inp = (const float*)d_in[0];
    const float* tgt = (const float*)d_in[1];
    // d_in[2] is the all-ones 9x9 filter; baked into the box sums.
    float* out = (float*)d_out;
    cc_kernel<<<NBLOCKS, 64>>>(inp, tgt, out);
}

// round 7
// speedup vs baseline: 1.0229x; 1.0229x over previous
#include <cuda_runtime.h>

typedef unsigned long long u64;

#define H 512
#define W 512
#define NB 32
#define OUTW 56            // output columns per warp (lanes 0..27 x 2)
#define STRIPS 10          // 10*56 = 560 >= 512
#define YSEGS 8
#define YLEN 64
#define WARPS_TOTAL (STRIPS * NB * YSEGS)   // 2560
#define WPB 2
#define NBLOCKS (WARPS_TOTAL / WPB)         // 1280
#define RP 256             // u64 (float2) row pitch

__device__ float g_part[NBLOCKS];
__device__ int   g_cnt = 0;

// ---- packed f32x2 helpers (sm_100a) ----
__device__ __forceinline__ u64 pk2(float x, float y) {
    u64 r; asm("mov.b64 %0,{%1,%2};" : "=l"(r) : "f"(x), "f"(y)); return r;
}
__device__ __forceinline__ void upk2(u64 v, float& x, float& y) {
    asm("mov.b64 {%0,%1},%2;" : "=f"(x), "=f"(y) : "l"(v));
}
__device__ __forceinline__ u64 fma2(u64 a, u64 b, u64 c) {
    u64 d; asm("fma.rn.f32x2 %0,%1,%2,%3;" : "=l"(d) : "l"(a), "l"(b), "l"(c)); return d;
}
__device__ __forceinline__ u64 add2(u64 a, u64 b) {
    u64 d; asm("add.rn.f32x2 %0,%1,%2;" : "=l"(d) : "l"(a), "l"(b)); return d;
}
__device__ __forceinline__ u64 mul2(u64 a, u64 b) {
    u64 d; asm("mul.rn.f32x2 %0,%1,%2;" : "=l"(d) : "l"(a), "l"(b)); return d;
}

// Pair-channel horizontal 9-window sums on scalar halves (valid lanes 0..27).
#define HSUM9P(a0, a1, hE, hO) do {                          \
    float _p  = (a0) + (a1);                                 \
    float _s  = _p + __shfl_down_sync(0xffffffffu, _p, 1);   \
    float _S4 = _s + __shfl_down_sync(0xffffffffu, _s, 2);   \
    (hE) = _S4  + __shfl_down_sync(0xffffffffu, (a0), 4);    \
    (hO) = (a1) + __shfl_down_sync(0xffffffffu, _S4, 1);     \
} while (0)

__global__ __launch_bounds__(64, 10) void cc_kernel(const float* __restrict__ inp,
                                                    const float* __restrict__ tgt,
                                                    float* __restrict__ out) {
    const int lane = threadIdx.x & 31;
    const int wid  = threadIdx.x >> 5;
    const int w    = blockIdx.x * WPB + wid;

    const int strip = w % STRIPS;
    const int rem   = w / STRIPS;          // 0..255
    const int b     = rem >> 3;            // 0..31
    const int y0    = (rem & 7) * YLEN;    // 0..448

    const int xs  = strip * OUTW;
    const int gx  = xs - 4 + 2 * lane;
    const bool cok = (unsigned)gx < W;

    const int ocolE = xs + 2 * lane;
    const bool valE = (lane < 28) && (ocolE     < W);
    const bool valO = (lane < 28) && (ocolE + 1 < W);

    const size_t boff = (size_t)b * (H * W) + (cok ? gx : 0);
    const u64* __restrict__ pI2 = (const u64*)(inp + boff);
    const u64* __restrict__ pT2 = (const u64*)(tgt + boff);

    const u64 HALF2  = pk2(0.5f, 0.5f);
    const u64 NEG1   = pk2(-1.0f, -1.0f);
    const u64 NINV81 = pk2(-1.0f / 81.0f, -1.0f / 81.0f);
    const u64 EPS2   = pk2(1e-5f, 1e-5f);

    // packed ring buffers: 2 x 9 u64 (= 36 regs), packed running sums (10 regs)
    u64 rI[9], rT[9];
    #pragma unroll
    for (int k = 0; k < 9; k++) { rI[k] = 0ull; rT[k] = 0ull; }
    u64 VA = 0ull, VB = 0ull, VAA = 0ull, VBB = 0ull, VAB = 0ull;
    float accE = 0.f, accO = 0.f;

    // emit one output row from current packed V sums
    auto emit = [&]() {
        float VA0, VA1, VB0, VB1, VAA0, VAA1, VBB0, VBB1, VAB0, VAB1;
        upk2(VA, VA0, VA1);  upk2(VB, VB0, VB1);
        upk2(VAA, VAA0, VAA1); upk2(VBB, VBB0, VBB1); upk2(VAB, VAB0, VAB1);
        float SAE, SAO, SBE, SBO, SAAE, SAAO, SBBE, SBBO, SABE, SABO;
        HSUM9P(VA0,  VA1,  SAE,  SAO);
        HSUM9P(VB0,  VB1,  SBE,  SBO);
        HSUM9P(VAA0, VAA1, SAAE, SAAO);
        HSUM9P(VBB0, VBB1, SBBE, SBBO);
        HSUM9P(VAB0, VAB1, SABE, SABO);
        const u64 S_A  = pk2(SAE,  SAO);
        const u64 S_B  = pk2(SBE,  SBO);
        const u64 S_AA = pk2(SAAE, SAAO);
        const u64 S_BB = pk2(SBBE, SBBO);
        const u64 S_AB = pk2(SABE, SABO);
        const u64 tAn   = mul2(S_A, NINV81);
        const u64 tBn   = mul2(S_B, NINV81);
        const u64 cross = fma2(tAn, S_B, S_AB);
        const u64 ivar  = fma2(tAn, S_A, S_AA);
        const u64 tvar  = fma2(tBn, S_B, S_BB);
        const u64 num   = mul2(cross, cross);
        const u64 den   = fma2(tvar, ivar, EPS2);
        float nE, nO, dE, dO;
        upk2(num, nE, nO);
        upk2(den, dE, dO);
        accE += valE ? __fdividef(nE, dE) : 0.f;
        accO += valO ? __fdividef(nO, dO) : 0.f;
    };

    // prefetch first row (gy = y0-4)
    u64 cI = 0ull, cT = 0ull;
    {
        const int gy = y0 - 4;
        if (cok && (unsigned)gy < H) {
            cI = __ldg(pI2 + (ptrdiff_t)gy * RP);
            const u64 traw = __ldg(pT2 + (ptrdiff_t)gy * RP);
            cT = fma2(traw, HALF2, HALF2);
        }
    }

    // ---- warmup: rows y0-4 .. y0+3 (8 add-only iterations) ----
    #pragma unroll
    for (int i = 0; i < 8; i++) {
        const int gy = y0 - 3 + i;
        u64 nI = 0ull, nT = 0ull;
        if (cok && (unsigned)gy < H) {
            nI = __ldg(pI2 + (ptrdiff_t)gy * RP);
            const u64 traw = __ldg(pT2 + (ptrdiff_t)gy * RP);
            nT = fma2(traw, HALF2, HALF2);
        }
        VA  = add2(VA, cI);
        VB  = add2(VB, cT);
        VAA = fma2(cI, cI, VAA);
        VBB = fma2(cT, cT, VBB);
        VAB = fma2(cI, cT, VAB);
        rI[i] = cI; rT[i] = cT;
        cI = nI; cT = nT;
    }
    // 9th row (y0+4) enters; first output row
    {
        const int gy = y0 + 5;
        u64 nI = 0ull, nT = 0ull;
        if (cok && (unsigned)gy < H) {
            nI = __ldg(pI2 + (ptrdiff_t)gy * RP);
            const u64 traw = __ldg(pT2 + (ptrdiff_t)gy * RP);
            nT = fma2(traw, HALF2, HALF2);
        }
        VA  = add2(VA, cI);
        VB  = add2(VB, cT);
        VAA = fma2(cI, cI, VAA);
        VBB = fma2(cT, cT, VBB);
        VAB = fma2(cI, cT, VAB);
        rI[8] = cI; rT[8] = cT;
        cI = nI; cT = nT;
        emit();
    }

    // ---- steady: 63 more output rows; ring slot cycles 0..8 ----
    #pragma unroll 1
    for (int j = 0; j < 7; j++) {
        #pragma unroll
        for (int k = 0; k < 9; k++) {
            const int i  = j * 9 + k;            // 0..62
            const int gy = y0 + 6 + i;           // next row to prefetch
            u64 nI = 0ull, nT = 0ull;
            if (cok && (unsigned)gy < H && i < 62) {
                nI = __ldg(pI2 + (ptrdiff_t)gy * RP);
                const u64 traw = __ldg(pT2 + (ptrdiff_t)gy * RP);
                nT = fma2(traw, HALF2, HALF2);
            }
            const u64 oi = rI[k], ot = rT[k];
            const u64 oin = mul2(oi, NEG1);
            const u64 otn = mul2(ot, NEG1);
            VA  = add2(VA, cI);   VA  = fma2(oi, NEG1, VA);
            VB  = add2(VB, cT);   VB  = fma2(ot, NEG1, VB);
            VAA = fma2(cI, cI, VAA);  VAA = fma2(oin, oi, VAA);
            VBB = fma2(cT, cT, VBB);  VBB = fma2(otn, ot, VBB);
            VAB = fma2(cI, cT, VAB);  VAB = fma2(oin, ot, VAB);
            rI[k] = cI; rT[k] = cT;
            cI = nI; cT = nT;
            emit();
        }
    }

    // ---- reduction: warp -> block -> global partials -> last block finishes ----
    float acc = accE + accO;
    #pragma unroll
    for (int off = 16; off > 0; off >>= 1)
        acc += __shfl_down_sync(0xffffffffu, acc, off);

    __shared__ float sred[WPB];
    __shared__ int   slast;
    if (lane == 0) sred[wid] = acc;
    __syncthreads();
    if (threadIdx.x == 0) {
        g_part[blockIdx.x] = sred[0] + sred[1];
        __threadfence();
        int old = atomicAdd(&g_cnt, 1);
        slast = (old == NBLOCKS - 1) ? 1 : 0;
    }
    __syncthreads();

    if (slast) {
        // 1280 partials = 320 float4; 64 threads -> 5 float4 each
        double d = 0.0;
        const float4* p4 = (const float4*)g_part;
        #pragma unroll
        for (int r = 0; r < 5; r++) {
            const float4 v = p4[threadIdx.x + r * 64];
            d += (double)v.x + (double)v.y + (double)v.z + (double)v.w;
        }
        #pragma unroll
        for (int off = 16; off > 0; off >>= 1)
            d += __shfl_down_sync(0xffffffffu, d, off);
        __shared__ double dred[WPB];
        if (lane == 0) dred[wid] = d;
        __syncthreads();
        if (threadIdx.x == 0) {
            out[0] = (float)(-(dred[0] + dred[1]) / 8388608.0);   // 32*512*512
            g_cnt = 0;                            // reset for next graph replay
        }
    }
}

extern "C" void kernel_launch(void* const* d_in, const int* in_sizes, int n_in,
                              void* d_out, int out_size) {
    const float* inp = (const float*)d_in[0];
    const float* tgt = (const float*)d_in[1];
    // d_in[2] is the all-ones 9x9 filter; baked into the box sums.
    float* out = (float*)d_out;
    cc_kernel<<<NBLOCKS, 64>>>(inp, tgt, out);
}